// round 13
// baseline (speedup 1.0000x reference)
#include <cuda_runtime.h>
#include <cuda_bf16.h>

// LocalitySensitiveHashing_29111288333011 — FINAL FORM (converged, R1-R12)
//
// Mathematical collapse (holds for ALL inputs, provable from the reference's
// constants alone): the 'bqhk,bkhk->bhqk' einsum has no contracted index
// (the repeated k on 'bkhk' is a diagonal extraction), so sim is an
// elementwise product of sign() values in {-1,0,+1}, scaled by 1/hash_bits
// (HB=2048) and averaged over H=8 heads:
//     |sim[b,q,k]| <= 1/HB = 4.88e-4  <  SIM_THRESHOLD = 0.3
// => (sim > 0.3) is identically False => output == zeros([2,2048,2048], f32).
// The optimal kernel is a pure 32 MiB zero-fill; no input is read.
//
// Convergence evidence (R1-R12): five write paths (STG.128 x1/x8 per thread,
// STG.256, driver memset node, TMA bulk store), two cache policies, two grid
// shapes, and six identical-config reruns. Stationary distribution: e2e mode
// 8.672us (5/10 samples; range 8.67-9.63), kernel 7.46-7.97us, DRAM=0%.
// Clock-normalized that is ~100% of the LTS write cap (6300 B/cyc at the
// ~0.7 GHz unramped DVFS clock of a microsecond kernel; ncu's ~37-38% is
// normalized to boost clock). e2e = L2-write wall + ~1us fixed replay
// overhead. Bytes fixed (d_out poisoned 0xAA), clocks harness-owned,
// overhead replay-fixed: no lever remains. Holding canonical best form.

#define ZF_THREADS 256
#define ZF_V       8                       // float4 per thread
#define ZF_TILE    (ZF_THREADS * ZF_V)     // 2048 float4 per block

__global__ __launch_bounds__(ZF_THREADS)
void lsh_zero_exact_kernel(float4* __restrict__ out) {
    // Exact-cover launch: no bounds checks on the hot path.
    unsigned int base = blockIdx.x * ZF_TILE + threadIdx.x;
    const float4 z = make_float4(0.0f, 0.0f, 0.0f, 0.0f);
    #pragma unroll
    for (int j = 0; j < ZF_V; j++) {
        __stcs(out + base + j * ZF_THREADS, z);   // st.global.cs.v4 (streaming)
    }
}

// Generic tail (never launched for this shape; kept for robustness).
__global__ void lsh_zero_tail_kernel(float* __restrict__ out, long long n) {
    long long i = (long long)blockIdx.x * blockDim.x + threadIdx.x;
    if (i < n) out[i] = 0.0f;
}

extern "C" void kernel_launch(void* const* d_in, const int* in_sizes, int n_in,
                              void* d_out, int out_size) {
    (void)d_in; (void)in_sizes; (void)n_in;

    float* out = (float*)d_out;
    long long n = (long long)out_size;        // 8,388,608 floats (32 MiB)

    long long n4      = n >> 2;               // float4 count
    long long blocks  = n4 / ZF_TILE;         // 1024 exact-cover blocks
    long long covered = blocks * (long long)ZF_TILE * 4;

    if (blocks > 0) {
        lsh_zero_exact_kernel<<<(unsigned int)blocks, ZF_THREADS>>>((float4*)out);
    }
    long long rem = n - covered;              // 0 for this shape
    if (rem > 0) {
        long long tb = (rem + 255) / 256;
        lsh_zero_tail_kernel<<<(unsigned int)tb, 256>>>(out + covered, rem);
    }
}